// round 4
// baseline (speedup 1.0000x reference)
#include <cuda_runtime.h>
#include <math.h>

#define BATCH 8
#define SEQL  4096
#define DM    256
#define HH    768
#define NST   32
#define TCH   64
#define NC    (SEQL/TCH)   // 64

// ---------------- scratch (static device globals; no allocation) ----------------
__device__ float g_gate [(size_t)BATCH*SEQL*HH];   // sigmoid(gate) [b][l][h]
__device__ float g_resid[(size_t)BATCH*SEQL*HH];   // [b][l][h]
__device__ float g_gated[(size_t)BATCH*HH*SEQL];   // [b][h][l]
__device__ float g_ys4  [(size_t)BATCH*HH*SEQL];   // [b][h][l]
__device__ float g_Wt   [25*DM*DM];                // [tap][c][o] transposed conv weights
__device__ float g_kern [HH*TCH];                  // first TCH taps of SSM kernel
__device__ float g_E    [HH*TCH*NST*2];            // [h][t][n][2] = Cd*lam^{t+1}
__device__ float g_P    [HH*TCH*NST*2];            // [h][t][n][2] = lam^{T-1-t}
__device__ float g_lamT [HH*NST*2];                // lam^T
__device__ float g_F    [(size_t)BATCH*HH*NC*NST*2];
__device__ float g_S    [(size_t)BATCH*HH*NC*NST*2]; // state entering each chunk

// ---------------- K0a: transpose conv weights to [tap][c][o] ----------------
__global__ void k_wt(const float* __restrict__ w0, const float* __restrict__ w1,
                     const float* __restrict__ w2) {
    int idx = blockIdx.x * 256 + threadIdx.x;       // total 25*256*256
    int o = idx & 255, c = (idx >> 8) & 255, tap = idx >> 16;
    const float* w; int k, K;
    if (tap < 3)       { w = w0; k = tap;      K = 3;  }
    else if (tap < 10) { w = w1; k = tap - 3;  K = 7;  }
    else               { w = w2; k = tap - 10; K = 15; }
    g_Wt[idx] = w[(o * DM + c) * K + k];
}

// ---------------- K0b: S4D tables ----------------
__global__ void k_s4prep(const float* __restrict__ log_dt, const float* __restrict__ A_re,
                         const float* __restrict__ A_im,  const float* __restrict__ C_re,
                         const float* __restrict__ C_im) {
    int h = blockIdx.x, n = threadIdx.x;            // 768 blocks x 32
    float dt  = expf(log_dt[h]);
    float ar  = A_re[h*NST+n], ai = A_im[h*NST+n];
    float dar = dt*ar, dai = dt*ai;
    float er  = expf(dar);
    float lr  = er*cosf(dai), li = er*sinf(dai);    // lambda = exp(dt*A)
    float nr  = lr - 1.f, ni = li;                  // exp(dtA)-1
    float cr  = C_re[h*NST+n], ci = C_im[h*NST+n];
    float t1r = cr*nr - ci*ni, t1i = cr*ni + ci*nr; // C*(exp(dtA)-1)
    float den = ar*ar + ai*ai;
    float cdr = (t1r*ar + t1i*ai)/den;              // /A
    float cdi = (t1i*ar - t1r*ai)/den;

    float pr = cdr, pi = cdi;                       // Cd * lambda^0
    for (int t = 0; t < TCH; t++) {
        float s = pr;
        #pragma unroll
        for (int off = 16; off; off >>= 1) s += __shfl_xor_sync(0xffffffffu, s, off);
        if (n == 0) g_kern[h*TCH + t] = 2.f*s;
        float npr = pr*lr - pi*li, npi = pr*li + pi*lr;   // -> Cd*lambda^{t+1}
        pr = npr; pi = npi;
        g_E[((h*TCH + t)*NST + n)*2 + 0] = pr;
        g_E[((h*TCH + t)*NST + n)*2 + 1] = pi;
    }
    float qr = 1.f, qi = 0.f;                       // lambda^m
    for (int m = 0; m < TCH; m++) {
        g_P[((h*TCH + (TCH-1-m))*NST + n)*2 + 0] = qr;
        g_P[((h*TCH + (TCH-1-m))*NST + n)*2 + 1] = qi;
        float nqr = qr*lr - qi*li, nqi = qr*li + qi*lr;
        qr = nqr; qi = nqi;
    }
    g_lamT[(h*NST+n)*2+0] = qr;                     // lambda^T
    g_lamT[(h*NST+n)*2+1] = qi;
}

// ---------------- K1: gate + res GEMMs: [32768,256] @ W^T[256,768] ----------------
__global__ __launch_bounds__(256) void k_gemm(const float* __restrict__ x,
        const float* __restrict__ gw, const float* __restrict__ gb,
        const float* __restrict__ rw, const float* __restrict__ rb) {
    __shared__ float Xs[64][65];
    __shared__ float Ws[64][65];
    int row0 = blockIdx.x * 64;
    int col0 = blockIdx.y * 64;
    int z    = blockIdx.z;                           // 0=gate 1=res
    const float* W = z ? rw : gw;
    int tr = threadIdx.x >> 4, tc = threadIdx.x & 15;
    float acc[4][4] = {};
    for (int c0 = 0; c0 < DM; c0 += 64) {
        __syncthreads();
        #pragma unroll
        for (int i = 0; i < 16; i++) {
            int lin = i*256 + threadIdx.x;
            int r = lin >> 6, c = lin & 63;
            Xs[c][r] = x[(size_t)(row0 + r)*DM + c0 + c];
        }
        #pragma unroll
        for (int i = 0; i < 16; i++) {
            int lin = i*256 + threadIdx.x;
            int o = lin >> 6, c = lin & 63;
            Ws[c][o] = W[(size_t)(col0 + o)*DM + c0 + c];
        }
        __syncthreads();
        #pragma unroll 16
        for (int cc = 0; cc < 64; cc++) {
            float a0 = Xs[cc][tr], a1 = Xs[cc][tr+16], a2 = Xs[cc][tr+32], a3 = Xs[cc][tr+48];
            float b0 = Ws[cc][tc], b1 = Ws[cc][tc+16], b2 = Ws[cc][tc+32], b3 = Ws[cc][tc+48];
            acc[0][0]+=a0*b0; acc[0][1]+=a0*b1; acc[0][2]+=a0*b2; acc[0][3]+=a0*b3;
            acc[1][0]+=a1*b0; acc[1][1]+=a1*b1; acc[1][2]+=a1*b2; acc[1][3]+=a1*b3;
            acc[2][0]+=a2*b0; acc[2][1]+=a2*b1; acc[2][2]+=a2*b2; acc[2][3]+=a2*b3;
            acc[3][0]+=a3*b0; acc[3][1]+=a3*b1; acc[3][2]+=a3*b2; acc[3][3]+=a3*b3;
        }
    }
    #pragma unroll
    for (int i = 0; i < 4; i++) {
        int row = row0 + tr + 16*i;
        #pragma unroll
        for (int j = 0; j < 4; j++) {
            int col = col0 + tc + 16*j;
            if (z == 0) {
                float v = acc[i][j] + gb[col];
                g_gate[(size_t)row*HH + col] = 1.f/(1.f + __expf(-v));
            } else {
                g_resid[(size_t)row*HH + col] = acc[i][j] + rb[col];
            }
        }
    }
}

// ---------------- K2: 3 dilated convs + gating; writes g_gated [b][h][l] ----------------
__global__ __launch_bounds__(256) void k_conv(const float* __restrict__ x,
        const float* __restrict__ cb0, const float* __restrict__ cb1,
        const float* __restrict__ cb2) {
    __shared__ float Us[120][64];    // l halo [-28, +91] x 64 channels
    __shared__ float Ws[64][65];     // per-tap weight chunk [c][o]
    int br   = blockIdx.y >> 2;
    int osub = (blockIdx.y & 3) * 64;
    int K, dil, tb; const float* cb;
    if (br == 0)      { K = 3;  dil = 1; tb = 0;  cb = cb0; }
    else if (br == 1) { K = 7;  dil = 2; tb = 3;  cb = cb1; }
    else              { K = 15; dil = 4; tb = 10; cb = cb2; }
    int l0 = blockIdx.x * 64;
    int b  = blockIdx.z;
    int tr = threadIdx.x >> 4, tc = threadIdx.x & 15;
    float acc[4][4] = {};
    for (int c0 = 0; c0 < DM; c0 += 64) {
        __syncthreads();
        #pragma unroll
        for (int i = 0; i < 30; i++) {
            int lin = i*256 + threadIdx.x;
            int j = lin >> 6, cc = lin & 63;
            int l = l0 - 28 + j;
            Us[j][cc] = ((unsigned)l < SEQL) ? x[((size_t)(b*SEQL + l))*DM + c0 + cc] : 0.f;
        }
        for (int k = 0; k < K; k++) {
            __syncthreads();
            #pragma unroll
            for (int i = 0; i < 16; i++) {
                int lin = i*256 + threadIdx.x;
                int cc = lin >> 6, o = lin & 63;
                Ws[cc][o] = g_Wt[(size_t)(tb + k)*65536 + (c0 + cc)*256 + osub + o];
            }
            __syncthreads();
            int off = (k - K/2) * dil;
            int lb  = 28 + off + tr;
            #pragma unroll 8
            for (int cc = 0; cc < 64; cc++) {
                float a0 = Us[lb][cc], a1 = Us[lb+16][cc], a2 = Us[lb+32][cc], a3 = Us[lb+48][cc];
                float b0 = Ws[cc][tc], b1 = Ws[cc][tc+16], b2 = Ws[cc][tc+32], b3 = Ws[cc][tc+48];
                acc[0][0]+=a0*b0; acc[0][1]+=a0*b1; acc[0][2]+=a0*b2; acc[0][3]+=a0*b3;
                acc[1][0]+=a1*b0; acc[1][1]+=a1*b1; acc[1][2]+=a1*b2; acc[1][3]+=a1*b3;
                acc[2][0]+=a2*b0; acc[2][1]+=a2*b1; acc[2][2]+=a2*b2; acc[2][3]+=a2*b3;
                acc[3][0]+=a3*b0; acc[3][1]+=a3*b1; acc[3][2]+=a3*b2; acc[3][3]+=a3*b3;
            }
        }
    }
    #pragma unroll
    for (int i = 0; i < 4; i++) {
        int l = l0 + tr + 16*i;
        #pragma unroll
        for (int j = 0; j < 4; j++) {
            int hc = osub + tc + 16*j;        // channel within branch
            int h  = br*256 + hc;
            float g = g_gate[((size_t)(b*SEQL + l))*HH + h];
            g_gated[((size_t)(b*HH + h))*SEQL + l] = (acc[i][j] + cb[hc]) * g;
        }
    }
}

// ---------------- K3: per-chunk state encode F[c] = sum_t lam^{63-t} u[cT+t] ----------------
__global__ __launch_bounds__(256) void k_F(void) {
    __shared__ float Ps[TCH*NST*2];   // 16KB
    __shared__ float us[SEQL];        // 16KB: whole (b,h) row
    int bh = blockIdx.x;              // b*HH + h
    int h  = bh % HH;
    for (int i = threadIdx.x; i < TCH*NST*2; i += 256) Ps[i] = g_P[(size_t)h*TCH*NST*2 + i];
    for (int i = threadIdx.x; i < SEQL; i += 256)      us[i] = g_gated[(size_t)bh*SEQL + i];
    __syncthreads();
    int w = threadIdx.x >> 5, n = threadIdx.x & 31;
    const float2* P2 = (const float2*)Ps;
    for (int c = w; c < NC; c += 8) {
        float ar = 0.f, ai = 0.f;
        int ub = c*TCH;
        #pragma unroll 8
        for (int t = 0; t < TCH; t++) {
            float u = us[ub + t];
            float2 p = P2[t*NST + n];
            ar += p.x * u; ai += p.y * u;
        }
        ((float2*)g_F)[((size_t)bh*NC + c)*NST + n] = make_float2(ar, ai);
    }
}

// ---------------- K4: cross-chunk scan: S[c] = state entering chunk c ----------------
__global__ __launch_bounds__(256) void k_scan(void) {
    int g = threadIdx.x >> 5, n = threadIdx.x & 31;
    int bh = blockIdx.x * 8 + g;
    int h  = bh % HH;
    float2 lam = ((const float2*)g_lamT)[h*NST + n];
    float sr = 0.f, si = 0.f;
    const float2* F2 = (const float2*)g_F;
    float2* S2 = (float2*)g_S;
    size_t base = (size_t)bh * NC * NST;
    for (int c = 0; c < NC; c++) {
        S2[base + c*NST + n] = make_float2(sr, si);
        float2 f = F2[base + c*NST + n];
        float nsr = sr*lam.x - si*lam.y + f.x;
        float nsi = sr*lam.y + si*lam.x + f.y;
        sr = nsr; si = nsi;
    }
}

// ---------------- K5: y = local conv + state decode + D*u ; writes g_ys4 [b][h][l] ----------------
__global__ __launch_bounds__(256) void k_y(const float* __restrict__ Dskip) {
    __shared__ float us[SEQL];          // 16KB
    __shared__ float2 Es[NST*TCH];      // 16KB, [n][t]
    __shared__ float kerns[TCH];
    int bh = blockIdx.x;
    int h  = bh % HH;
    for (int i = threadIdx.x; i < SEQL; i += 256) us[i] = g_gated[(size_t)bh*SEQL + i];
    const float2* gE2 = (const float2*)g_E;
    for (int i = threadIdx.x; i < TCH*NST; i += 256) {
        int t = i >> 5, n = i & 31;
        Es[n*TCH + t] = gE2[(size_t)h*TCH*NST + i];
    }
    if (threadIdx.x < TCH) kerns[threadIdx.x] = g_kern[h*TCH + threadIdx.x];
    __syncthreads();
    float dsk = Dskip[h];
    int w = threadIdx.x >> 5, lane = threadIdx.x & 31;
    const float2* S2 = (const float2*)g_S;
    for (int c = w; c < NC; c += 8) {
        float2 s = S2[((size_t)bh*NC + c)*NST + lane];
        int ub = c*TCH;
        int t0 = lane, t1 = lane + 32;
        float y0 = 0.f, y1 = 0.f;
        #pragma unroll 8
        for (int j = 0; j < TCH; j++) {
            float kj = kerns[j];
            if (j <= t0) y0 += kj * us[ub + t0 - j];
            if (j <= t1) y1 += kj * us[ub + t1 - j];
        }
        #pragma unroll 8
        for (int n = 0; n < NST; n++) {
            float snr = __shfl_sync(0xffffffffu, s.x, n);
            float sni = __shfl_sync(0xffffffffu, s.y, n);
            float2 e0 = Es[n*TCH + t0];
            float2 e1 = Es[n*TCH + t1];
            y0 += 2.f*(e0.x*snr - e0.y*sni);
            y1 += 2.f*(e1.x*snr - e1.y*sni);
        }
        y0 += dsk * us[ub + t0];
        y1 += dsk * us[ub + t1];
        g_ys4[(size_t)bh*SEQL + ub + t0] = y0;
        g_ys4[(size_t)bh*SEQL + ub + t1] = y1;
    }
}

// ---------------- K6: transpose + residual + LayerNorm -> out [b][l][h] ----------------
__global__ __launch_bounds__(256) void k_ln(const float* __restrict__ gamma,
                                            const float* __restrict__ beta,
                                            float* __restrict__ out) {
    __shared__ float tile[8][770];   // 8 l x 768 h (+pad)
    int b  = blockIdx.y;
    int l0 = blockIdx.x * 8;
    for (int hh = threadIdx.x; hh < HH; hh += 256) {
        const float4* p = (const float4*)(g_ys4 + ((size_t)(b*HH + hh))*SEQL + l0);
        float4 v0 = p[0], v1 = p[1];
        tile[0][hh] = v0.x; tile[1][hh] = v0.y; tile[2][hh] = v0.z; tile[3][hh] = v0.w;
        tile[4][hh] = v1.x; tile[5][hh] = v1.y; tile[6][hh] = v1.z; tile[7][hh] = v1.w;
    }
    __syncthreads();
    int w = threadIdx.x >> 5, lane = threadIdx.x & 31;
    int l = l0 + w;
    size_t rbase = ((size_t)(b*SEQL + l))*HH;
    float s = 0.f, s2 = 0.f;
    for (int hh = lane; hh < HH; hh += 32) {
        float y = tile[w][hh] + g_resid[rbase + hh];
        tile[w][hh] = y;
        s += y; s2 += y*y;
    }
    #pragma unroll
    for (int off = 16; off; off >>= 1) {
        s  += __shfl_xor_sync(0xffffffffu, s,  off);
        s2 += __shfl_xor_sync(0xffffffffu, s2, off);
    }
    float mu   = s * (1.f/HH);
    float var  = s2 * (1.f/HH) - mu*mu;
    float rstd = rsqrtf(var + 1e-5f);
    for (int hh = lane; hh < HH; hh += 32) {
        out[rbase + hh] = (tile[w][hh] - mu) * rstd * gamma[hh] + beta[hh];
    }
}

extern "C" void kernel_launch(void* const* d_in, const int* in_sizes, int n_in,
                              void* d_out, int out_size) {
    const float* x      = (const float*)d_in[0];
    const float* cw0    = (const float*)d_in[1];
    const float* cb0    = (const float*)d_in[2];
    const float* cw1    = (const float*)d_in[3];
    const float* cb1    = (const float*)d_in[4];
    const float* cw2    = (const float*)d_in[5];
    const float* cb2    = (const float*)d_in[6];
    const float* gw     = (const float*)d_in[7];
    const float* gb     = (const float*)d_in[8];
    const float* rw     = (const float*)d_in[9];
    const float* rb     = (const float*)d_in[10];
    const float* log_dt = (const float*)d_in[11];
    const float* A_re   = (const float*)d_in[12];
    const float* A_im   = (const float*)d_in[13];
    const float* C_re   = (const float*)d_in[14];
    const float* C_im   = (const float*)d_in[15];
    const float* Dskip  = (const float*)d_in[16];
    const float* lng    = (const float*)d_in[17];
    const float* lnb    = (const float*)d_in[18];
    float* out = (float*)d_out;

    k_wt<<<25*256, 256>>>(cw0, cw1, cw2);
    k_s4prep<<<HH, NST>>>(log_dt, A_re, A_im, C_re, C_im);
    k_gemm<<<dim3(512, 12, 2), 256>>>(x, gw, gb, rw, rb);
    k_conv<<<dim3(64, 12, 8), 256>>>(x, cb0, cb1, cb2);
    k_F<<<BATCH*HH, 256>>>();
    k_scan<<<BATCH*HH/8, 256>>>();
    k_y<<<BATCH*HH, 256>>>(Dskip);
    k_ln<<<dim3(SEQL/8, BATCH), 256>>>(lng, lnb, out);
}

// round 7
// speedup vs baseline: 2.5316x; 2.5316x over previous
#include <cuda_runtime.h>
#include <math.h>

#define BATCH 8
#define SEQL  4096
#define DM    256
#define HH    768
#define NST   32
#define TCH   64
#define NC    (SEQL/TCH)   // 64

// ---------------- scratch (static device globals; no allocation) ----------------
__device__ float g_gate [(size_t)BATCH*HH*SEQL];   // sigmoid(gate) TRANSPOSED [b][h][l]
__device__ float g_resid[(size_t)BATCH*SEQL*HH];   // [b][l][h]
__device__ float g_gated[(size_t)BATCH*HH*SEQL];   // [b][h][l]
__device__ float g_ys4  [(size_t)BATCH*HH*SEQL];   // [b][h][l]
__device__ float g_Wt   [25*DM*DM];                // [tap][o][c], tf32-rounded
__device__ float g_kern [HH*TCH];                  // first TCH taps of SSM kernel
__device__ float g_E    [HH*TCH*NST*2];            // [h][t][n][2] = Cd*lam^{t+1}
__device__ float g_P    [HH*TCH*NST*2];            // [h][t][n][2] = lam^{T-1-t}
__device__ float g_lamT [HH*NST*2];                // lam^T
__device__ float g_F    [(size_t)BATCH*HH*NC*NST*2];
__device__ float g_S    [(size_t)BATCH*HH*NC*NST*2];

__device__ __forceinline__ unsigned f2tf(float f) {
    unsigned u; asm("cvt.rna.tf32.f32 %0, %1;" : "=r"(u) : "f"(f)); return u;
}
__device__ __forceinline__ void mma_tf32(float c[4], const unsigned a[4], const unsigned b[2]) {
    asm volatile("mma.sync.aligned.m16n8k8.row.col.f32.tf32.tf32.f32 "
        "{%0,%1,%2,%3}, {%4,%5,%6,%7}, {%8,%9}, {%0,%1,%2,%3};"
        : "+f"(c[0]), "+f"(c[1]), "+f"(c[2]), "+f"(c[3])
        : "r"(a[0]), "r"(a[1]), "r"(a[2]), "r"(a[3]), "r"(b[0]), "r"(b[1]));
}

// ---------------- K0a: conv weights -> [tap][o][c], tf32-rounded ----------------
__global__ void k_wt(const float* __restrict__ w0, const float* __restrict__ w1,
                     const float* __restrict__ w2) {
    int idx = blockIdx.x * 256 + threadIdx.x;       // tap<<16 | o<<8 | c
    int c = idx & 255, o = (idx >> 8) & 255, tap = idx >> 16;
    const float* w; int k, K;
    if (tap < 3)       { w = w0; k = tap;      K = 3;  }
    else if (tap < 10) { w = w1; k = tap - 3;  K = 7;  }
    else               { w = w2; k = tap - 10; K = 15; }
    g_Wt[idx] = __uint_as_float(f2tf(w[(o * DM + c) * K + k]));
}

// ---------------- K0b: S4D tables ----------------
__global__ void k_s4prep(const float* __restrict__ log_dt, const float* __restrict__ A_re,
                         const float* __restrict__ A_im,  const float* __restrict__ C_re,
                         const float* __restrict__ C_im) {
    int h = blockIdx.x, n = threadIdx.x;
    float dt  = expf(log_dt[h]);
    float ar  = A_re[h*NST+n], ai = A_im[h*NST+n];
    float dar = dt*ar, dai = dt*ai;
    float er  = expf(dar);
    float lr  = er*cosf(dai), li = er*sinf(dai);
    float nr  = lr - 1.f, ni = li;
    float cr  = C_re[h*NST+n], ci = C_im[h*NST+n];
    float t1r = cr*nr - ci*ni, t1i = cr*ni + ci*nr;
    float den = ar*ar + ai*ai;
    float cdr = (t1r*ar + t1i*ai)/den;
    float cdi = (t1i*ar - t1r*ai)/den;

    float pr = cdr, pi = cdi;
    for (int t = 0; t < TCH; t++) {
        float s = pr;
        #pragma unroll
        for (int off = 16; off; off >>= 1) s += __shfl_xor_sync(0xffffffffu, s, off);
        if (n == 0) g_kern[h*TCH + t] = 2.f*s;
        float npr = pr*lr - pi*li, npi = pr*li + pi*lr;
        pr = npr; pi = npi;
        g_E[((h*TCH + t)*NST + n)*2 + 0] = pr;
        g_E[((h*TCH + t)*NST + n)*2 + 1] = pi;
    }
    float qr = 1.f, qi = 0.f;
    for (int m = 0; m < TCH; m++) {
        g_P[((h*TCH + (TCH-1-m))*NST + n)*2 + 0] = qr;
        g_P[((h*TCH + (TCH-1-m))*NST + n)*2 + 1] = qi;
        float nqr = qr*lr - qi*li, nqi = qr*li + qi*lr;
        qr = nqr; qi = nqi;
    }
    g_lamT[(h*NST+n)*2+0] = qr;
    g_lamT[(h*NST+n)*2+1] = qi;
}

// ---------------- K1: gate + res projections via tf32 mma ----------------
// grid (256, 6, 2): m-tile 128 rows of [b*l], n-tile 128 of h, z: 0=gate 1=res
__global__ __launch_bounds__(256, 2) void k_gemm(const float* __restrict__ x,
        const float* __restrict__ gw, const float* __restrict__ gb,
        const float* __restrict__ rw, const float* __restrict__ rb) {
    extern __shared__ unsigned sm[];
    unsigned* Xs = sm;              // [128][68]
    unsigned* Ws = sm + 128*68;     // [128][68]  (rows = h, cols = c)
    int row0 = blockIdx.x * 128;
    int col0 = blockIdx.y * 128;
    int z    = blockIdx.z;
    const float* W  = z ? rw : gw;
    const float* Bv = z ? rb : gb;
    int tid = threadIdx.x, lane = tid & 31, wp = tid >> 5;
    int mw = (wp & 3) * 32, nw = (wp >> 2) * 64;
    int r_lo = lane >> 2, tg = lane & 3;
    float acc[2][8][4] = {};
    for (int c0 = 0; c0 < DM; c0 += 64) {
        __syncthreads();
        #pragma unroll
        for (int i = 0; i < 8; i++) {
            int lin = i*256 + tid; int r = lin >> 4, q = lin & 15;
            float4 v = *(const float4*)(x + (size_t)(row0 + r)*DM + c0 + 4*q);
            uint4 t = make_uint4(f2tf(v.x), f2tf(v.y), f2tf(v.z), f2tf(v.w));
            *(uint4*)(Xs + r*68 + 4*q) = t;
        }
        #pragma unroll
        for (int i = 0; i < 8; i++) {
            int lin = i*256 + tid; int r = lin >> 4, q = lin & 15;
            float4 v = *(const float4*)(W + (size_t)(col0 + r)*DM + c0 + 4*q);
            uint4 t = make_uint4(f2tf(v.x), f2tf(v.y), f2tf(v.z), f2tf(v.w));
            *(uint4*)(Ws + r*68 + 4*q) = t;
        }
        __syncthreads();
        #pragma unroll
        for (int kk = 0; kk < 64; kk += 8) {
            unsigned a[2][4], b[8][2];
            #pragma unroll
            for (int mt = 0; mt < 2; mt++) {
                int base = (mw + mt*16 + r_lo)*68 + kk + tg;
                a[mt][0] = Xs[base];       a[mt][1] = Xs[base + 8*68];
                a[mt][2] = Xs[base + 4];   a[mt][3] = Xs[base + 8*68 + 4];
            }
            #pragma unroll
            for (int nt = 0; nt < 8; nt++) {
                int bb = (nw + nt*8 + r_lo)*68 + kk + tg;
                b[nt][0] = Ws[bb]; b[nt][1] = Ws[bb + 4];
            }
            #pragma unroll
            for (int mt = 0; mt < 2; mt++)
                #pragma unroll
                for (int nt = 0; nt < 8; nt++)
                    mma_tf32(acc[mt][nt], a[mt], b[nt]);
        }
    }
    if (z == 1) {   // residual: direct [b*l][h]
        #pragma unroll
        for (int mt = 0; mt < 2; mt++)
            #pragma unroll
            for (int nt = 0; nt < 8; nt++)
                #pragma unroll
                for (int rr = 0; rr < 2; rr++) {
                    int row = row0 + mw + mt*16 + r_lo + rr*8;
                    int col = col0 + nw + nt*8 + 2*tg;
                    float2 v = make_float2(acc[mt][nt][rr*2+0] + Bv[col],
                                           acc[mt][nt][rr*2+1] + Bv[col+1]);
                    *(float2*)(g_resid + (size_t)row*HH + col) = v;
                }
    } else {        // gate: sigmoid + transpose-stage -> g_gate[b][h][l]
        __syncthreads();
        float* tile = (float*)sm;   // [128 h][132 l]
        #pragma unroll
        for (int mt = 0; mt < 2; mt++)
            #pragma unroll
            for (int nt = 0; nt < 8; nt++)
                #pragma unroll
                for (int rr = 0; rr < 2; rr++) {
                    int m = mw + mt*16 + r_lo + rr*8;
                    int n = nw + nt*8 + 2*tg;
                    float v0 = acc[mt][nt][rr*2+0] + Bv[col0+n];
                    float v1 = acc[mt][nt][rr*2+1] + Bv[col0+n+1];
                    tile[n*132 + m]     = 1.f/(1.f + __expf(-v0));
                    tile[(n+1)*132 + m] = 1.f/(1.f + __expf(-v1));
                }
        __syncthreads();
        int b = row0 / SEQL, l0 = row0 % SEQL;
        int hh = tid >> 1, l_off = (tid & 1) * 64;
        float* dst = g_gate + ((size_t)(b*HH) + col0 + hh)*SEQL + l0 + l_off;
        #pragma unroll
        for (int q = 0; q < 16; q++)
            *(float4*)(dst + 4*q) = *(float4*)(tile + hh*132 + l_off + 4*q);
    }
}

// ---------------- K2: dilated convs via tf32 mma + gating -> g_gated [b][h][l] ----------------
// grid (32, 6, 8): 128 l-tile, y: br=y>>1 half=y&1 (128 o), z: batch
__global__ __launch_bounds__(256, 2) void k_conv(const float* __restrict__ x,
        const float* __restrict__ cb0, const float* __restrict__ cb1,
        const float* __restrict__ cb2) {
    extern __shared__ unsigned sm[];
    unsigned* Us = sm;                // [184][68]
    unsigned* Ws = sm + 184*68;       // [128 o][68 c]
    int br   = blockIdx.y >> 1;
    int o0   = (blockIdx.y & 1) * 128;
    int K, dil, tb; const float* cb;
    if (br == 0)      { K = 3;  dil = 1; tb = 0;  cb = cb0; }
    else if (br == 1) { K = 7;  dil = 2; tb = 3;  cb = cb1; }
    else              { K = 15; dil = 4; tb = 10; cb = cb2; }
    int l0 = blockIdx.x * 128;
    int b  = blockIdx.z;
    int tid = threadIdx.x, lane = tid & 31, wp = tid >> 5;
    int mw = (wp & 3) * 32, nw = (wp >> 2) * 64;
    int r_lo = lane >> 2, tg = lane & 3;
    float acc[2][8][4] = {};
    const unsigned* Wtu = (const unsigned*)g_Wt;
    for (int c0 = 0; c0 < DM; c0 += 64) {
        __syncthreads();
        #pragma unroll
        for (int i = 0; i < 12; i++) {
            int lin = i*256 + tid;
            if (lin < 2944) {
                int r = lin >> 4, q = lin & 15;
                int l = l0 - 28 + r;
                uint4 t = make_uint4(0u, 0u, 0u, 0u);
                if ((unsigned)l < SEQL) {
                    float4 v = *(const float4*)(x + ((size_t)(b*SEQL + l))*DM + c0 + 4*q);
                    t = make_uint4(f2tf(v.x), f2tf(v.y), f2tf(v.z), f2tf(v.w));
                }
                *(uint4*)(Us + r*68 + 4*q) = t;
            }
        }
        for (int k = 0; k < K; k++) {
            __syncthreads();
            #pragma unroll
            for (int i = 0; i < 8; i++) {
                int lin = i*256 + tid; int r = lin >> 4, q = lin & 15;
                *(uint4*)(Ws + r*68 + 4*q) =
                    *(const uint4*)(Wtu + (size_t)(tb + k)*65536 + (o0 + r)*256 + c0 + 4*q);
            }
            __syncthreads();
            int lb = 28 + (k - K/2) * dil;
            #pragma unroll
            for (int kk = 0; kk < 64; kk += 8) {
                unsigned a[2][4], bfr[8][2];
                #pragma unroll
                for (int mt = 0; mt < 2; mt++) {
                    int base = (lb + mw + mt*16 + r_lo)*68 + kk + tg;
                    a[mt][0] = Us[base];       a[mt][1] = Us[base + 8*68];
                    a[mt][2] = Us[base + 4];   a[mt][3] = Us[base + 8*68 + 4];
                }
                #pragma unroll
                for (int nt = 0; nt < 8; nt++) {
                    int bb = (nw + nt*8 + r_lo)*68 + kk + tg;
                    bfr[nt][0] = Ws[bb]; bfr[nt][1] = Ws[bb + 4];
                }
                #pragma unroll
                for (int mt = 0; mt < 2; mt++)
                    #pragma unroll
                    for (int nt = 0; nt < 8; nt++)
                        mma_tf32(acc[mt][nt], a[mt], bfr[nt]);
            }
        }
    }
    // epilogue: stage [o][l], then bias+gate+store coalesced along l
    __syncthreads();
    float* tile = (float*)sm;   // [128 o][132 l]
    #pragma unroll
    for (int mt = 0; mt < 2; mt++)
        #pragma unroll
        for (int nt = 0; nt < 8; nt++)
            #pragma unroll
            for (int rr = 0; rr < 2; rr++) {
                int m = mw + mt*16 + r_lo + rr*8;
                int n = nw + nt*8 + 2*tg;
                tile[n*132 + m]     = acc[mt][nt][rr*2+0];
                tile[(n+1)*132 + m] = acc[mt][nt][rr*2+1];
            }
    __syncthreads();
    int hh = tid >> 1, l_off = (tid & 1) * 64;
    int hglob = br*256 + o0 + hh;
    float bias = cb[o0 + hh];
    const float* gp = g_gate  + ((size_t)(b*HH) + hglob)*SEQL + l0 + l_off;
    float*       op = g_gated + ((size_t)(b*HH) + hglob)*SEQL + l0 + l_off;
    #pragma unroll
    for (int q = 0; q < 16; q++) {
        float4 a = *(float4*)(tile + hh*132 + l_off + 4*q);
        float4 g = *(const float4*)(gp + 4*q);
        *(float4*)(op + 4*q) = make_float4((a.x+bias)*g.x, (a.y+bias)*g.y,
                                           (a.z+bias)*g.z, (a.w+bias)*g.w);
    }
}

// ---------------- K3: per-chunk state encode ----------------
__global__ __launch_bounds__(256) void k_F(void) {
    __shared__ float Ps[TCH*NST*2];
    __shared__ float us[SEQL];
    int bh = blockIdx.x;
    int h  = bh % HH;
    for (int i = threadIdx.x; i < TCH*NST*2; i += 256) Ps[i] = g_P[(size_t)h*TCH*NST*2 + i];
    for (int i = threadIdx.x; i < SEQL; i += 256)      us[i] = g_gated[(size_t)bh*SEQL + i];
    __syncthreads();
    int w = threadIdx.x >> 5, n = threadIdx.x & 31;
    const float2* P2 = (const float2*)Ps;
    for (int c = w; c < NC; c += 8) {
        float ar = 0.f, ai = 0.f;
        int ub = c*TCH;
        #pragma unroll 8
        for (int t = 0; t < TCH; t++) {
            float u = us[ub + t];
            float2 p = P2[t*NST + n];
            ar += p.x * u; ai += p.y * u;
        }
        ((float2*)g_F)[((size_t)bh*NC + c)*NST + n] = make_float2(ar, ai);
    }
}

// ---------------- K4: cross-chunk scan ----------------
__global__ __launch_bounds__(256) void k_scan(void) {
    int g = threadIdx.x >> 5, n = threadIdx.x & 31;
    int bh = blockIdx.x * 8 + g;
    int h  = bh % HH;
    float2 lam = ((const float2*)g_lamT)[h*NST + n];
    float sr = 0.f, si = 0.f;
    const float2* F2 = (const float2*)g_F;
    float2* S2 = (float2*)g_S;
    size_t base = (size_t)bh * NC * NST;
    for (int c = 0; c < NC; c++) {
        S2[base + c*NST + n] = make_float2(sr, si);
        float2 f = F2[base + c*NST + n];
        float nsr = sr*lam.x - si*lam.y + f.x;
        float nsi = sr*lam.y + si*lam.x + f.y;
        sr = nsr; si = nsi;
    }
}

// ---------------- K5: local conv + state decode + D*u ----------------
__global__ __launch_bounds__(256) void k_y(const float* __restrict__ Dskip) {
    __shared__ float us[SEQL];
    __shared__ float2 Es[NST*TCH];
    __shared__ float kerns[TCH];
    int bh = blockIdx.x;
    int h  = bh % HH;
    for (int i = threadIdx.x; i < SEQL; i += 256) us[i] = g_gated[(size_t)bh*SEQL + i];
    const float2* gE2 = (const float2*)g_E;
    for (int i = threadIdx.x; i < TCH*NST; i += 256) {
        int t = i >> 5, n = i & 31;
        Es[n*TCH + t] = gE2[(size_t)h*TCH*NST + i];
    }
    if (threadIdx.x < TCH) kerns[threadIdx.x] = g_kern[h*TCH + threadIdx.x];
    __syncthreads();
    float dsk = Dskip[h];
    int w = threadIdx.x >> 5, lane = threadIdx.x & 31;
    const float2* S2 = (const float2*)g_S;
    for (int c = w; c < NC; c += 8) {
        float2 s = S2[((size_t)bh*NC + c)*NST + lane];
        int ub = c*TCH;
        int t0 = lane, t1 = lane + 32;
        float y0 = 0.f, y1 = 0.f;
        #pragma unroll 8
        for (int j = 0; j < TCH; j++) {
            float kj = kerns[j];
            if (j <= t0) y0 += kj * us[ub + t0 - j];
            if (j <= t1) y1 += kj * us[ub + t1 - j];
        }
        #pragma unroll 8
        for (int n = 0; n < NST; n++) {
            float snr = __shfl_sync(0xffffffffu, s.x, n);
            float sni = __shfl_sync(0xffffffffu, s.y, n);
            float2 e0 = Es[n*TCH + t0];
            float2 e1 = Es[n*TCH + t1];
            y0 += 2.f*(e0.x*snr - e0.y*sni);
            y1 += 2.f*(e1.x*snr - e1.y*sni);
        }
        y0 += dsk * us[ub + t0];
        y1 += dsk * us[ub + t1];
        g_ys4[(size_t)bh*SEQL + ub + t0] = y0;
        g_ys4[(size_t)bh*SEQL + ub + t1] = y1;
    }
}

// ---------------- K6: transpose + residual + LayerNorm ----------------
__global__ __launch_bounds__(256) void k_ln(const float* __restrict__ gamma,
                                            const float* __restrict__ beta,
                                            float* __restrict__ out) {
    __shared__ float tile[8][770];
    int b  = blockIdx.y;
    int l0 = blockIdx.x * 8;
    for (int hh = threadIdx.x; hh < HH; hh += 256) {
        const float4* p = (const float4*)(g_ys4 + ((size_t)(b*HH + hh))*SEQL + l0);
        float4 v0 = p[0], v1 = p[1];
        tile[0][hh] = v0.x; tile[1][hh] = v0.y; tile[2][hh] = v0.z; tile[3][hh] = v0.w;
        tile[4][hh] = v1.x; tile[5][hh] = v1.y; tile[6][hh] = v1.z; tile[7][hh] = v1.w;
    }
    __syncthreads();
    int w = threadIdx.x >> 5, lane = threadIdx.x & 31;
    int l = l0 + w;
    size_t rbase = ((size_t)(b*SEQL + l))*HH;
    float s = 0.f, s2 = 0.f;
    for (int hh = lane; hh < HH; hh += 32) {
        float y = tile[w][hh] + g_resid[rbase + hh];
        tile[w][hh] = y;
        s += y; s2 += y*y;
    }
    #pragma unroll
    for (int off = 16; off; off >>= 1) {
        s  += __shfl_xor_sync(0xffffffffu, s,  off);
        s2 += __shfl_xor_sync(0xffffffffu, s2, off);
    }
    float mu   = s * (1.f/HH);
    float var  = s2 * (1.f/HH) - mu*mu;
    float rstd = rsqrtf(var + 1e-5f);
    for (int hh = lane; hh < HH; hh += 32) {
        out[rbase + hh] = (tile[w][hh] - mu) * rstd * gamma[hh] + beta[hh];
    }
}

extern "C" void kernel_launch(void* const* d_in, const int* in_sizes, int n_in,
                              void* d_out, int out_size) {
    const float* x      = (const float*)d_in[0];
    const float* cw0    = (const float*)d_in[1];
    const float* cb0    = (const float*)d_in[2];
    const float* cw1    = (const float*)d_in[3];
    const float* cb1    = (const float*)d_in[4];
    const float* cw2    = (const float*)d_in[5];
    const float* cb2    = (const float*)d_in[6];
    const float* gw     = (const float*)d_in[7];
    const float* gb     = (const float*)d_in[8];
    const float* rw     = (const float*)d_in[9];
    const float* rb     = (const float*)d_in[10];
    const float* log_dt = (const float*)d_in[11];
    const float* A_re   = (const float*)d_in[12];
    const float* A_im   = (const float*)d_in[13];
    const float* C_re   = (const float*)d_in[14];
    const float* C_im   = (const float*)d_in[15];
    const float* Dskip  = (const float*)d_in[16];
    const float* lng    = (const float*)d_in[17];
    const float* lnb    = (const float*)d_in[18];
    float* out = (float*)d_out;

    const int GEMM_SMEM = 2 * 128 * 68 * 4;          // 69632 B
    const int CONV_SMEM = (184*68 + 128*68) * 4;     // 84864 B
    cudaFuncSetAttribute(k_gemm, cudaFuncAttributeMaxDynamicSharedMemorySize, GEMM_SMEM);
    cudaFuncSetAttribute(k_conv, cudaFuncAttributeMaxDynamicSharedMemorySize, CONV_SMEM);

    k_wt<<<25*256, 256>>>(cw0, cw1, cw2);
    k_s4prep<<<HH, NST>>>(log_dt, A_re, A_im, C_re, C_im);
    k_gemm<<<dim3(256, 6, 2), 256, GEMM_SMEM>>>(x, gw, gb, rw, rb);
    k_conv<<<dim3(32, 6, 8), 256, CONV_SMEM>>>(x, cb0, cb1, cb2);
    k_F<<<BATCH*HH, 256>>>();
    k_scan<<<BATCH*HH/8, 256>>>();
    k_y<<<BATCH*HH, 256>>>(Dskip);
    k_ln<<<dim3(SEQL/8, BATCH), 256>>>(lng, lnb, out);
}

// round 8
// speedup vs baseline: 3.7797x; 1.4930x over previous
#include <cuda_runtime.h>
#include <math.h>

#define BATCH 8
#define SEQL  4096
#define DM    256
#define HH    768
#define NST   32
#define TCH   64
#define NC    (SEQL/TCH)   // 64

// ---------------- scratch (static device globals; no allocation) ----------------
__device__ float g_gate [(size_t)BATCH*HH*SEQL];   // sigmoid(gate) TRANSPOSED [b][h][l]
__device__ float g_resid[(size_t)BATCH*SEQL*HH];   // [b][l][h]
__device__ float g_gated[(size_t)BATCH*HH*SEQL];   // [b][h][l]
__device__ float g_ys4  [(size_t)BATCH*HH*SEQL];   // [b][h][l]
__device__ float g_Wt   [25*DM*DM];                // [tap][o][c], tf32-rounded
__device__ float g_kern [HH*TCH];                  // first TCH taps of SSM kernel
__device__ float g_E    [HH*TCH*NST*2];            // [h][t][n][2] = Cd*lam^{t+1}
__device__ float g_P    [HH*TCH*NST*2];            // [h][t][n][2] = lam^{T-1-t}
__device__ float g_lamT [HH*NST*2];                // lam^T
__device__ float g_F    [(size_t)BATCH*HH*NC*NST*2];   // [bh][c][64nri]
__device__ float g_S    [(size_t)BATCH*HH*NC*NST*2];   // [bh][c][64nri]
// GEMM-layout S4D tables (tf32-rounded), all [h][64][64]:
__device__ float g_Pm   [(size_t)HH*TCH*TCH];      // [h][nri][t]
__device__ float g_Tm   [(size_t)HH*TCH*TCH];      // [h][tout][tin] Toeplitz (+Dskip diag)
__device__ float g_Dm   [(size_t)HH*TCH*TCH];      // [h][tout][nri]

__device__ __forceinline__ unsigned f2tf(float f) {
    unsigned u; asm("cvt.rna.tf32.f32 %0, %1;" : "=r"(u) : "f"(f)); return u;
}
__device__ __forceinline__ void mma_tf32(float c[4], const unsigned a[4], const unsigned b[2]) {
    asm volatile("mma.sync.aligned.m16n8k8.row.col.f32.tf32.tf32.f32 "
        "{%0,%1,%2,%3}, {%4,%5,%6,%7}, {%8,%9}, {%0,%1,%2,%3};"
        : "+f"(c[0]), "+f"(c[1]), "+f"(c[2]), "+f"(c[3])
        : "r"(a[0]), "r"(a[1]), "r"(a[2]), "r"(a[3]), "r"(b[0]), "r"(b[1]));
}

// ---------------- K0a: conv weights -> [tap][o][c], tf32-rounded ----------------
__global__ void k_wt(const float* __restrict__ w0, const float* __restrict__ w1,
                     const float* __restrict__ w2) {
    int idx = blockIdx.x * 256 + threadIdx.x;       // tap<<16 | o<<8 | c
    int c = idx & 255, o = (idx >> 8) & 255, tap = idx >> 16;
    const float* w; int k, K;
    if (tap < 3)       { w = w0; k = tap;      K = 3;  }
    else if (tap < 10) { w = w1; k = tap - 3;  K = 7;  }
    else               { w = w2; k = tap - 10; K = 15; }
    g_Wt[idx] = __uint_as_float(f2tf(w[(o * DM + c) * K + k]));
}

// ---------------- K0b: S4D parameter tables ----------------
__global__ void k_s4prep(const float* __restrict__ log_dt, const float* __restrict__ A_re,
                         const float* __restrict__ A_im,  const float* __restrict__ C_re,
                         const float* __restrict__ C_im) {
    int h = blockIdx.x, n = threadIdx.x;
    float dt  = expf(log_dt[h]);
    float ar  = A_re[h*NST+n], ai = A_im[h*NST+n];
    float dar = dt*ar, dai = dt*ai;
    float er  = expf(dar);
    float lr  = er*cosf(dai), li = er*sinf(dai);
    float nr  = lr - 1.f, ni = li;
    float cr  = C_re[h*NST+n], ci = C_im[h*NST+n];
    float t1r = cr*nr - ci*ni, t1i = cr*ni + ci*nr;
    float den = ar*ar + ai*ai;
    float cdr = (t1r*ar + t1i*ai)/den;
    float cdi = (t1i*ar - t1r*ai)/den;

    float pr = cdr, pi = cdi;
    for (int t = 0; t < TCH; t++) {
        float s = pr;
        #pragma unroll
        for (int off = 16; off; off >>= 1) s += __shfl_xor_sync(0xffffffffu, s, off);
        if (n == 0) g_kern[h*TCH + t] = 2.f*s;
        float npr = pr*lr - pi*li, npi = pr*li + pi*lr;
        pr = npr; pi = npi;
        g_E[((h*TCH + t)*NST + n)*2 + 0] = pr;
        g_E[((h*TCH + t)*NST + n)*2 + 1] = pi;
    }
    float qr = 1.f, qi = 0.f;
    for (int m = 0; m < TCH; m++) {
        g_P[((h*TCH + (TCH-1-m))*NST + n)*2 + 0] = qr;
        g_P[((h*TCH + (TCH-1-m))*NST + n)*2 + 1] = qi;
        float nqr = qr*lr - qi*li, nqi = qr*li + qi*lr;
        qr = nqr; qi = nqi;
    }
    g_lamT[(h*NST+n)*2+0] = qr;
    g_lamT[(h*NST+n)*2+1] = qi;
}

// ---------------- K0c: GEMM-layout tables Pm/Tm/Dm ----------------
__global__ void k_tables(const float* __restrict__ Dskip) {
    int h = blockIdx.x;
    float dsk = Dskip[h];
    for (int i = threadIdx.x; i < TCH*TCH; i += 256) {
        // Pm[nri][t] = lam^{63-t} component
        int nri = i >> 6, t = i & 63;
        int n = nri >> 1, ri = nri & 1;
        g_Pm[(size_t)h*4096 + i] = __uint_as_float(f2tf(g_P[((h*TCH + t)*NST + n)*2 + ri]));
        // Dm[tout][nri] = +2*E_re / -2*E_im
        int to = i >> 6, nri2 = i & 63;
        int n2 = nri2 >> 1, ri2 = nri2 & 1;
        float e = g_E[((h*TCH + to)*NST + n2)*2 + ri2];
        g_Dm[(size_t)h*4096 + i] = __uint_as_float(f2tf(ri2 ? -2.f*e : 2.f*e));
        // Tm[tout][tin] = kern[tout-tin] (lower-tri) + Dskip on diag
        int ti = i & 63;
        float v = 0.f;
        if (to >= ti) { v = g_kern[h*TCH + (to - ti)]; if (to == ti) v += dsk; }
        g_Tm[(size_t)h*4096 + i] = __uint_as_float(f2tf(v));
    }
}

// ---------------- K1: gate + res projections via tf32 mma ----------------
__global__ __launch_bounds__(256, 2) void k_gemm(const float* __restrict__ x,
        const float* __restrict__ gw, const float* __restrict__ gb,
        const float* __restrict__ rw, const float* __restrict__ rb) {
    extern __shared__ unsigned sm[];
    unsigned* Xs = sm;              // [128][68]
    unsigned* Ws = sm + 128*68;     // [128][68]
    int row0 = blockIdx.x * 128;
    int col0 = blockIdx.y * 128;
    int z    = blockIdx.z;
    const float* W  = z ? rw : gw;
    const float* Bv = z ? rb : gb;
    int tid = threadIdx.x, lane = tid & 31, wp = tid >> 5;
    int mw = (wp & 3) * 32, nw = (wp >> 2) * 64;
    int r_lo = lane >> 2, tg = lane & 3;
    float acc[2][8][4] = {};
    for (int c0 = 0; c0 < DM; c0 += 64) {
        __syncthreads();
        #pragma unroll
        for (int i = 0; i < 8; i++) {
            int lin = i*256 + tid; int r = lin >> 4, q = lin & 15;
            float4 v = *(const float4*)(x + (size_t)(row0 + r)*DM + c0 + 4*q);
            *(uint4*)(Xs + r*68 + 4*q) = make_uint4(f2tf(v.x), f2tf(v.y), f2tf(v.z), f2tf(v.w));
        }
        #pragma unroll
        for (int i = 0; i < 8; i++) {
            int lin = i*256 + tid; int r = lin >> 4, q = lin & 15;
            float4 v = *(const float4*)(W + (size_t)(col0 + r)*DM + c0 + 4*q);
            *(uint4*)(Ws + r*68 + 4*q) = make_uint4(f2tf(v.x), f2tf(v.y), f2tf(v.z), f2tf(v.w));
        }
        __syncthreads();
        #pragma unroll
        for (int kk = 0; kk < 64; kk += 8) {
            unsigned a[2][4], b[8][2];
            #pragma unroll
            for (int mt = 0; mt < 2; mt++) {
                int base = (mw + mt*16 + r_lo)*68 + kk + tg;
                a[mt][0] = Xs[base];       a[mt][1] = Xs[base + 8*68];
                a[mt][2] = Xs[base + 4];   a[mt][3] = Xs[base + 8*68 + 4];
            }
            #pragma unroll
            for (int nt = 0; nt < 8; nt++) {
                int bb = (nw + nt*8 + r_lo)*68 + kk + tg;
                b[nt][0] = Ws[bb]; b[nt][1] = Ws[bb + 4];
            }
            #pragma unroll
            for (int mt = 0; mt < 2; mt++)
                #pragma unroll
                for (int nt = 0; nt < 8; nt++)
                    mma_tf32(acc[mt][nt], a[mt], b[nt]);
        }
    }
    if (z == 1) {
        #pragma unroll
        for (int mt = 0; mt < 2; mt++)
            #pragma unroll
            for (int nt = 0; nt < 8; nt++)
                #pragma unroll
                for (int rr = 0; rr < 2; rr++) {
                    int row = row0 + mw + mt*16 + r_lo + rr*8;
                    int col = col0 + nw + nt*8 + 2*tg;
                    float2 v = make_float2(acc[mt][nt][rr*2+0] + Bv[col],
                                           acc[mt][nt][rr*2+1] + Bv[col+1]);
                    *(float2*)(g_resid + (size_t)row*HH + col) = v;
                }
    } else {
        __syncthreads();
        float* tile = (float*)sm;   // [128 h][132 l]
        #pragma unroll
        for (int mt = 0; mt < 2; mt++)
            #pragma unroll
            for (int nt = 0; nt < 8; nt++)
                #pragma unroll
                for (int rr = 0; rr < 2; rr++) {
                    int m = mw + mt*16 + r_lo + rr*8;
                    int n = nw + nt*8 + 2*tg;
                    float v0 = acc[mt][nt][rr*2+0] + Bv[col0+n];
                    float v1 = acc[mt][nt][rr*2+1] + Bv[col0+n+1];
                    tile[n*132 + m]     = 1.f/(1.f + __expf(-v0));
                    tile[(n+1)*132 + m] = 1.f/(1.f + __expf(-v1));
                }
        __syncthreads();
        int b = row0 / SEQL, l0 = row0 % SEQL;
        int hh = tid >> 1, l_off = (tid & 1) * 64;
        float* dst = g_gate + ((size_t)(b*HH) + col0 + hh)*SEQL + l0 + l_off;
        #pragma unroll
        for (int q = 0; q < 16; q++)
            *(float4*)(dst + 4*q) = *(float4*)(tile + hh*132 + l_off + 4*q);
    }
}

// ---------------- K2: dilated convs via tf32 mma + gating -> g_gated [b][h][l] ----------------
__global__ __launch_bounds__(256, 2) void k_conv(const float* __restrict__ x,
        const float* __restrict__ cb0, const float* __restrict__ cb1,
        const float* __restrict__ cb2) {
    extern __shared__ unsigned sm[];
    unsigned* Us = sm;                // [184][68]
    unsigned* Ws = sm + 184*68;       // [128 o][68 c]
    int br   = blockIdx.y >> 1;
    int o0   = (blockIdx.y & 1) * 128;
    int K, dil, tb; const float* cb;
    if (br == 0)      { K = 3;  dil = 1; tb = 0;  cb = cb0; }
    else if (br == 1) { K = 7;  dil = 2; tb = 3;  cb = cb1; }
    else              { K = 15; dil = 4; tb = 10; cb = cb2; }
    int l0 = blockIdx.x * 128;
    int b  = blockIdx.z;
    int tid = threadIdx.x, lane = tid & 31, wp = tid >> 5;
    int mw = (wp & 3) * 32, nw = (wp >> 2) * 64;
    int r_lo = lane >> 2, tg = lane & 3;
    float acc[2][8][4] = {};
    const unsigned* Wtu = (const unsigned*)g_Wt;
    for (int c0 = 0; c0 < DM; c0 += 64) {
        __syncthreads();
        #pragma unroll
        for (int i = 0; i < 12; i++) {
            int lin = i*256 + tid;
            if (lin < 2944) {
                int r = lin >> 4, q = lin & 15;
                int l = l0 - 28 + r;
                uint4 t = make_uint4(0u, 0u, 0u, 0u);
                if ((unsigned)l < SEQL) {
                    float4 v = *(const float4*)(x + ((size_t)(b*SEQL + l))*DM + c0 + 4*q);
                    t = make_uint4(f2tf(v.x), f2tf(v.y), f2tf(v.z), f2tf(v.w));
                }
                *(uint4*)(Us + r*68 + 4*q) = t;
            }
        }
        for (int k = 0; k < K; k++) {
            __syncthreads();
            #pragma unroll
            for (int i = 0; i < 8; i++) {
                int lin = i*256 + tid; int r = lin >> 4, q = lin & 15;
                *(uint4*)(Ws + r*68 + 4*q) =
                    *(const uint4*)(Wtu + (size_t)(tb + k)*65536 + (o0 + r)*256 + c0 + 4*q);
            }
            __syncthreads();
            int lb = 28 + (k - K/2) * dil;
            #pragma unroll
            for (int kk = 0; kk < 64; kk += 8) {
                unsigned a[2][4], bfr[8][2];
                #pragma unroll
                for (int mt = 0; mt < 2; mt++) {
                    int base = (lb + mw + mt*16 + r_lo)*68 + kk + tg;
                    a[mt][0] = Us[base];       a[mt][1] = Us[base + 8*68];
                    a[mt][2] = Us[base + 4];   a[mt][3] = Us[base + 8*68 + 4];
                }
                #pragma unroll
                for (int nt = 0; nt < 8; nt++) {
                    int bb = (nw + nt*8 + r_lo)*68 + kk + tg;
                    bfr[nt][0] = Ws[bb]; bfr[nt][1] = Ws[bb + 4];
                }
                #pragma unroll
                for (int mt = 0; mt < 2; mt++)
                    #pragma unroll
                    for (int nt = 0; nt < 8; nt++)
                        mma_tf32(acc[mt][nt], a[mt], bfr[nt]);
            }
        }
    }
    __syncthreads();
    float* tile = (float*)sm;   // [128 o][132 l]
    #pragma unroll
    for (int mt = 0; mt < 2; mt++)
        #pragma unroll
        for (int nt = 0; nt < 8; nt++)
            #pragma unroll
            for (int rr = 0; rr < 2; rr++) {
                int m = mw + mt*16 + r_lo + rr*8;
                int n = nw + nt*8 + 2*tg;
                tile[n*132 + m]     = acc[mt][nt][rr*2+0];
                tile[(n+1)*132 + m] = acc[mt][nt][rr*2+1];
            }
    __syncthreads();
    int hh = tid >> 1, l_off = (tid & 1) * 64;
    int hglob = br*256 + o0 + hh;
    float bias = cb[o0 + hh];
    const float* gp = g_gate  + ((size_t)(b*HH) + hglob)*SEQL + l0 + l_off;
    float*       op = g_gated + ((size_t)(b*HH) + hglob)*SEQL + l0 + l_off;
    #pragma unroll
    for (int q = 0; q < 16; q++) {
        float4 a = *(float4*)(tile + hh*132 + l_off + 4*q);
        float4 g = *(const float4*)(gp + 4*q);
        *(float4*)(op + 4*q) = make_float4((a.x+bias)*g.x, (a.y+bias)*g.y,
                                           (a.z+bias)*g.z, (a.w+bias)*g.w);
    }
}

// ---------------- 64x64x64 tf32 GEMM helpers (1 block = 4 warps, m16 x n64 each) ----------------
__device__ __forceinline__ void load_tile_tf32(unsigned* dst, const float* src, int tid) {
    const float4* p = (const float4*)src;
    #pragma unroll
    for (int i = 0; i < 8; i++) {
        int lin = i*128 + tid; int r = lin >> 4, q = lin & 15;
        float4 v = p[lin];
        *(uint4*)(dst + r*68 + 4*q) = make_uint4(f2tf(v.x), f2tf(v.y), f2tf(v.z), f2tf(v.w));
    }
}
__device__ __forceinline__ void load_tile_raw(unsigned* dst, const unsigned* src, int tid) {
    const uint4* p = (const uint4*)src;
    #pragma unroll
    for (int i = 0; i < 8; i++) {
        int lin = i*128 + tid; int r = lin >> 4, q = lin & 15;
        *(uint4*)(dst + r*68 + 4*q) = p[lin];
    }
}
__device__ __forceinline__ void gemm64(float acc[8][4], const unsigned* As, const unsigned* Bs,
                                       int m0, int r_lo, int tg) {
    #pragma unroll
    for (int kk = 0; kk < 64; kk += 8) {
        unsigned a[4];
        int base = (m0 + r_lo)*68 + kk + tg;
        a[0] = As[base];       a[1] = As[base + 8*68];
        a[2] = As[base + 4];   a[3] = As[base + 8*68 + 4];
        #pragma unroll
        for (int nt = 0; nt < 8; nt++) {
            unsigned b[2]; int bb = (nt*8 + r_lo)*68 + kk + tg;
            b[0] = Bs[bb]; b[1] = Bs[bb + 4];
            mma_tf32(acc[nt], a, b);
        }
    }
}

// ---------------- K3: encode F[c][nri] = sum_t U[c][t] * Pm[nri][t] ----------------
__global__ __launch_bounds__(128) void k_enc(void) {
    __shared__ unsigned Us[64*68], Ps[64*68];
    int bh = blockIdx.x, h = bh % HH, tid = threadIdx.x;
    load_tile_tf32(Us, g_gated + (size_t)bh*SEQL, tid);
    load_tile_raw (Ps, (const unsigned*)g_Pm + (size_t)h*4096, tid);
    __syncthreads();
    int lane = tid & 31, wp = tid >> 5, m0 = wp*16, r_lo = lane >> 2, tg = lane & 3;
    float acc[8][4] = {};
    gemm64(acc, Us, Ps, m0, r_lo, tg);
    #pragma unroll
    for (int nt = 0; nt < 8; nt++) {
        int col = nt*8 + 2*tg;
        float* f = g_F + (size_t)bh*4096 + (m0 + r_lo)*64 + col;
        *(float2*)f         = make_float2(acc[nt][0], acc[nt][1]);
        *(float2*)(f + 512) = make_float2(acc[nt][2], acc[nt][3]);
    }
}

// ---------------- K4: cross-chunk scan ----------------
__global__ __launch_bounds__(256) void k_scan(void) {
    int g = threadIdx.x >> 5, n = threadIdx.x & 31;
    int bh = blockIdx.x * 8 + g;
    int h  = bh % HH;
    float2 lam = ((const float2*)g_lamT)[h*NST + n];
    float sr = 0.f, si = 0.f;
    const float2* F2 = (const float2*)g_F;
    float2* S2 = (float2*)g_S;
    size_t base = (size_t)bh * NC * NST;
    for (int c = 0; c < NC; c++) {
        S2[base + c*NST + n] = make_float2(sr, si);
        float2 f = F2[base + c*NST + n];
        float nsr = sr*lam.x - si*lam.y + f.x;
        float nsi = sr*lam.y + si*lam.x + f.y;
        sr = nsr; si = nsi;
    }
}

// ---------------- K5: decode Y = U*Tm^T + S*Dm^T -> g_ys4 [b][h][l] ----------------
__global__ __launch_bounds__(128) void k_dec(void) {
    __shared__ unsigned As[64*68], Bs[64*68];
    int bh = blockIdx.x, h = bh % HH, tid = threadIdx.x;
    load_tile_tf32(As, g_gated + (size_t)bh*SEQL, tid);
    load_tile_raw (Bs, (const unsigned*)g_Tm + (size_t)h*4096, tid);
    __syncthreads();
    int lane = tid & 31, wp = tid >> 5, m0 = wp*16, r_lo = lane >> 2, tg = lane & 3;
    float acc[8][4] = {};
    gemm64(acc, As, Bs, m0, r_lo, tg);
    __syncthreads();
    load_tile_tf32(As, g_S + (size_t)bh*4096, tid);
    load_tile_raw (Bs, (const unsigned*)g_Dm + (size_t)h*4096, tid);
    __syncthreads();
    gemm64(acc, As, Bs, m0, r_lo, tg);
    #pragma unroll
    for (int nt = 0; nt < 8; nt++) {
        int col = nt*8 + 2*tg;
        float* f = g_ys4 + (size_t)bh*SEQL + (m0 + r_lo)*64 + col;
        *(float2*)f         = make_float2(acc[nt][0], acc[nt][1]);
        *(float2*)(f + 512) = make_float2(acc[nt][2], acc[nt][3]);
    }
}

// ---------------- K6: transpose + residual + LayerNorm ----------------
__global__ __launch_bounds__(256) void k_ln(const float* __restrict__ gamma,
                                            const float* __restrict__ beta,
                                            float* __restrict__ out) {
    __shared__ float tile[16][768];   // exactly 48KB
    int b  = blockIdx.y;
    int l0 = blockIdx.x * 16;
    for (int hh = threadIdx.x; hh < HH; hh += 256) {
        const float4* p = (const float4*)(g_ys4 + ((size_t)(b*HH + hh))*SEQL + l0);
        #pragma unroll
        for (int q = 0; q < 4; q++) {
            float4 v = p[q];
            tile[4*q+0][hh] = v.x; tile[4*q+1][hh] = v.y;
            tile[4*q+2][hh] = v.z; tile[4*q+3][hh] = v.w;
        }
    }
    __syncthreads();
    int w = threadIdx.x >> 5, lane = threadIdx.x & 31;
    #pragma unroll
    for (int rr = 0; rr < 2; rr++) {
        int j = w + rr*8;
        int l = l0 + j;
        size_t rbase = ((size_t)(b*SEQL + l))*HH;
        float s = 0.f, s2 = 0.f;
        for (int hh = lane; hh < HH; hh += 32) {
            float y = tile[j][hh] + g_resid[rbase + hh];
            tile[j][hh] = y;
            s += y; s2 += y*y;
        }
        #pragma unroll
        for (int off = 16; off; off >>= 1) {
            s  += __shfl_xor_sync(0xffffffffu, s,  off);
            s2 += __shfl_xor_sync(0xffffffffu, s2, off);
        }
        float mu   = s * (1.f/HH);
        float var  = s2 * (1.f/HH) - mu*mu;
        float rstd = rsqrtf(var + 1e-5f);
        for (int hh = lane; hh < HH; hh += 32) {
            out[rbase + hh] = (tile[j][hh] - mu) * rstd * gamma[hh] + beta[hh];
        }
    }
}

extern "C" void kernel_launch(void* const* d_in, const int* in_sizes, int n_in,
                              void* d_out, int out_size) {
    const float* x      = (const float*)d_in[0];
    const float* cw0    = (const float*)d_in[1];
    const float* cb0    = (const float*)d_in[2];
    const float* cw1    = (const float*)d_in[3];
    const float* cb1    = (const float*)d_in[4];
    const float* cw2    = (const float*)d_in[5];
    const float* cb2    = (const float*)d_in[6];
    const float* gw     = (const float*)d_in[7];
    const float* gb     = (const float*)d_in[8];
    const float* rw     = (const float*)d_in[9];
    const float* rb     = (const float*)d_in[10];
    const float* log_dt = (const float*)d_in[11];
    const float* A_re   = (const float*)d_in[12];
    const float* A_im   = (const float*)d_in[13];
    const float* C_re   = (const float*)d_in[14];
    const float* C_im   = (const float*)d_in[15];
    const float* Dskip  = (const float*)d_in[16];
    const float* lng    = (const float*)d_in[17];
    const float* lnb    = (const float*)d_in[18];
    float* out = (float*)d_out;

    const int GEMM_SMEM = 2 * 128 * 68 * 4;          // 69632 B
    const int CONV_SMEM = (184*68 + 128*68) * 4;     // 84864 B
    cudaFuncSetAttribute(k_gemm, cudaFuncAttributeMaxDynamicSharedMemorySize, GEMM_SMEM);
    cudaFuncSetAttribute(k_conv, cudaFuncAttributeMaxDynamicSharedMemorySize, CONV_SMEM);

    k_wt<<<25*256, 256>>>(cw0, cw1, cw2);
    k_s4prep<<<HH, NST>>>(log_dt, A_re, A_im, C_re, C_im);
    k_tables<<<HH, 256>>>(Dskip);
    k_gemm<<<dim3(256, 6, 2), 256, GEMM_SMEM>>>(x, gw, gb, rw, rb);
    k_conv<<<dim3(32, 6, 8), 256, CONV_SMEM>>>(x, cb0, cb1, cb2);
    k_enc<<<BATCH*HH, 128>>>();
    k_scan<<<BATCH*HH/8, 256>>>();
    k_dec<<<BATCH*HH, 128>>>();
    k_ln<<<dim3(SEQL/16, BATCH), 256>>>(lng, lnb, out);
}